// round 1
// baseline (speedup 1.0000x reference)
#include <cuda_runtime.h>

// ===========================================================================
// MHA_73607149519311 — round 1: algebraically-restructured fp32 baseline.
//
// Reference:
//   h = leaky_relu(x) @ W_enc^T + b_enc
//   S = (ha WQ)(h WK)^T * SCALE ; P = softmax(S) * m ; prob = P/(sum+eps)
//   z = prob @ (h WV) ; out = mean_h z
//
// Restructured:
//   M_h  = WQ_h @ WK_h^T                       (8 x 256x256x256)
//   G    = ha @ M_h                            (256 x 256x256x256)
//   S    = G @ h^T * SCALE                     (256 x 256x1024x256)
//   prob = e*m / (sum(e*m) + eps*Z)            (exact masked-renorm identity)
//   U    = prob @ h                            (256 x 256x256x1024)
//   out  = 1/8 * sum_h U_h @ WV_h              (32  x 256x256x2048)
// ===========================================================================

namespace {
constexpr int kB = 32;
constexpr int kN = 1024;
constexpr int kA = 256;
constexpr int kD = 256;
constexpr int kH = 8;
constexpr float kScale = 1.0f / 16.0f;   // 1/sqrt(256)
constexpr float kEps = 1e-12f;
}

// Scratch (static device globals; no dynamic allocation allowed)
__device__ float g_h[(size_t)kB * kN * kD];        //  33.5 MB
__device__ float g_M[(size_t)kH * kD * kD];        //   2.1 MB
__device__ float g_G[(size_t)kB * kH * kA * kD];   //  67 MB
__device__ float g_S[(size_t)kB * kH * kA * kN];   // 268 MB
__device__ float g_U[(size_t)kB * kH * kA * kD];   //  67 MB

__device__ __forceinline__ float leaky01(float v) {
    return v > 0.0f ? v : 0.01f * v;
}

// ---------------------------------------------------------------------------
// 128x128x8 fp32 SGEMM mainloop, 256 threads, 8x8 per-thread microtile.
// A is row-major [M,K]. NT: B row-major [N,K] (C = A B^T).
//                        NN: B row-major [K,N] (C = A B).
// Requires M,N multiples of 128, K multiple of 8 (true for every call here).
// ---------------------------------------------------------------------------
template <bool NT, bool LEAKY>
__device__ __forceinline__ void gemm_mainloop(
    const float* __restrict__ A, const float* __restrict__ B,
    int lda, int ldb, int K, int row0, int col0,
    float (&acc)[8][8], float* __restrict__ As, float* __restrict__ Bs)
{
    const int tid = threadIdx.x;
    const int am  = tid >> 1;          // 0..127
    const int ak  = (tid & 1) << 2;    // 0 or 4
    const int bkr = tid >> 5;          // 0..7   (NN B load)
    const int bn  = (tid & 31) << 2;   // 0..124 (NN B load)
    const int tx  = tid & 15;
    const int ty  = tid >> 4;

    const float* aPtr   = A + (size_t)(row0 + am) * lda + ak;
    const float* bPtrNT = B + (size_t)(col0 + am) * ldb + ak;
    const float* bPtrNN = B + (size_t)bkr * ldb + col0 + bn;

    for (int kt = 0; kt < K; kt += 8) {
        float4 av = *(const float4*)(aPtr + kt);
        if (LEAKY) {
            av.x = leaky01(av.x); av.y = leaky01(av.y);
            av.z = leaky01(av.z); av.w = leaky01(av.w);
        }
        As[(ak + 0) * 132 + am] = av.x;
        As[(ak + 1) * 132 + am] = av.y;
        As[(ak + 2) * 132 + am] = av.z;
        As[(ak + 3) * 132 + am] = av.w;
        if (NT) {
            float4 bv = *(const float4*)(bPtrNT + kt);
            Bs[(ak + 0) * 132 + am] = bv.x;
            Bs[(ak + 1) * 132 + am] = bv.y;
            Bs[(ak + 2) * 132 + am] = bv.z;
            Bs[(ak + 3) * 132 + am] = bv.w;
        } else {
            float4 bv = *(const float4*)(bPtrNN + (size_t)kt * ldb);
            *(float4*)(Bs + bkr * 132 + bn) = bv;
        }
        __syncthreads();
#pragma unroll
        for (int k = 0; k < 8; k++) {
            float ar[8], br[8];
            *(float4*)(ar)     = *(const float4*)(As + k * 132 + ty * 8);
            *(float4*)(ar + 4) = *(const float4*)(As + k * 132 + ty * 8 + 4);
            *(float4*)(br)     = *(const float4*)(Bs + k * 132 + tx * 8);
            *(float4*)(br + 4) = *(const float4*)(Bs + k * 132 + tx * 8 + 4);
#pragma unroll
            for (int i = 0; i < 8; i++)
#pragma unroll
                for (int j = 0; j < 8; j++)
                    acc[i][j] = fmaf(ar[i], br[j], acc[i][j]);
        }
        __syncthreads();
    }
}

__device__ __forceinline__ void gemm_epilogue(
    float* __restrict__ C, int ldc, int row0, int col0,
    float (&acc)[8][8], float alpha, const float* __restrict__ bias)
{
    const int tx = threadIdx.x & 15;
    const int ty = threadIdx.x >> 4;
    float bv[8];
#pragma unroll
    for (int j = 0; j < 8; j++)
        bv[j] = bias ? bias[col0 + tx * 8 + j] : 0.0f;
#pragma unroll
    for (int i = 0; i < 8; i++) {
        float* cp = C + (size_t)(row0 + ty * 8 + i) * ldc + col0 + tx * 8;
        float4 v0, v1;
        v0.x = fmaf(alpha, acc[i][0], bv[0]);
        v0.y = fmaf(alpha, acc[i][1], bv[1]);
        v0.z = fmaf(alpha, acc[i][2], bv[2]);
        v0.w = fmaf(alpha, acc[i][3], bv[3]);
        v1.x = fmaf(alpha, acc[i][4], bv[4]);
        v1.y = fmaf(alpha, acc[i][5], bv[5]);
        v1.z = fmaf(alpha, acc[i][6], bv[6]);
        v1.w = fmaf(alpha, acc[i][7], bv[7]);
        *(float4*)cp       = v0;
        *(float4*)(cp + 4) = v1;
    }
}

// ---------------------------------------------------------------------------
// Kernels
// ---------------------------------------------------------------------------

// h = leaky_relu(x) @ W_enc^T + b_enc.  M=B*N=32768, N=256, K=256 (NT).
__global__ __launch_bounds__(256) void enc_kernel(
    const float* __restrict__ x, const float* __restrict__ W,
    const float* __restrict__ bias)
{
    __shared__ float As[8 * 132], Bs[8 * 132];
    float acc[8][8] = {};
    const int row0 = blockIdx.y * 128, col0 = blockIdx.x * 128;
    gemm_mainloop<true, true>(x, W, kD, kD, kD, row0, col0, acc, As, Bs);
    gemm_epilogue(g_h, kD, row0, col0, acc, 1.0f, bias);
}

// M_h = WQ_h @ WK_h^T.  batch=8, 256x256x256 (NT).
__global__ __launch_bounds__(256) void m_kernel(
    const float* __restrict__ WQ, const float* __restrict__ WK)
{
    __shared__ float As[8 * 132], Bs[8 * 132];
    float acc[8][8] = {};
    const int hh = blockIdx.z;
    const int row0 = blockIdx.y * 128, col0 = blockIdx.x * 128;
    gemm_mainloop<true, false>(WQ + (size_t)hh * kD * kD,
                               WK + (size_t)hh * kD * kD,
                               kD, kD, kD, row0, col0, acc, As, Bs);
    gemm_epilogue(g_M + (size_t)hh * kD * kD, kD, row0, col0, acc, 1.0f, nullptr);
}

// G[b,h] = ha[b] @ M_h.  batch=256, 256x256x256 (NN).
__global__ __launch_bounds__(256) void g_kernel()
{
    __shared__ float As[8 * 132], Bs[8 * 132];
    float acc[8][8] = {};
    const int z = blockIdx.z, b = z >> 3, hh = z & 7;
    const int row0 = blockIdx.y * 128, col0 = blockIdx.x * 128;
    gemm_mainloop<false, false>(g_h + (size_t)b * kN * kD,
                                g_M + (size_t)hh * kD * kD,
                                kD, kD, kD, row0, col0, acc, As, Bs);
    gemm_epilogue(g_G + (size_t)z * kA * kD, kD, row0, col0, acc, 1.0f, nullptr);
}

// S[b,h] = G[b,h] @ h[b]^T * SCALE.  batch=256, 256x1024x256 (NT).
__global__ __launch_bounds__(256) void s_kernel()
{
    __shared__ float As[8 * 132], Bs[8 * 132];
    float acc[8][8] = {};
    const int z = blockIdx.z, b = z >> 3;
    const int row0 = blockIdx.y * 128, col0 = blockIdx.x * 128;
    gemm_mainloop<true, false>(g_G + (size_t)z * kA * kD,
                               g_h + (size_t)b * kN * kD,
                               kD, kD, kD, row0, col0, acc, As, Bs);
    gemm_epilogue(g_S + (size_t)z * kA * kN, kN, row0, col0, acc, kScale, nullptr);
}

// In-place masked renormalized softmax on g_S rows:
// prob_i = e_i*m_i / (sum_j e_j*m_j + eps*Z),  e_i = exp(S_i - max), Z = sum e_j
__global__ __launch_bounds__(256) void softmax_kernel(const float* __restrict__ mglob)
{
    const int idx = blockIdx.x;          // (b*8+h)*256 + a
    const int a = idx & 255;
    const int b = idx >> 11;
    float* row = g_S + (size_t)idx * kN;
    const float* mrow = mglob + ((size_t)b * kA + a) * kN;
    const int tid = threadIdx.x;

    float v[4], mv[4];
#pragma unroll
    for (int i = 0; i < 4; i++) {
        v[i]  = row[tid + i * 256];
        mv[i] = mrow[tid + i * 256];
    }
    float lmax = fmaxf(fmaxf(v[0], v[1]), fmaxf(v[2], v[3]));
#pragma unroll
    for (int o = 16; o > 0; o >>= 1)
        lmax = fmaxf(lmax, __shfl_xor_sync(0xffffffffu, lmax, o));

    __shared__ float redmax[8], redz[8], redm[8], bc[2];
    const int warp = tid >> 5, lane = tid & 31;
    if (lane == 0) redmax[warp] = lmax;
    __syncthreads();
    if (tid == 0) {
        float mx = redmax[0];
        for (int w = 1; w < 8; w++) mx = fmaxf(mx, redmax[w]);
        bc[0] = mx;
    }
    __syncthreads();
    const float mx = bc[0];

    float e[4], zs = 0.0f, ms = 0.0f;
#pragma unroll
    for (int i = 0; i < 4; i++) {
        e[i] = expf(v[i] - mx);
        zs += e[i];
        ms += e[i] * mv[i];
    }
#pragma unroll
    for (int o = 16; o > 0; o >>= 1) {
        zs += __shfl_xor_sync(0xffffffffu, zs, o);
        ms += __shfl_xor_sync(0xffffffffu, ms, o);
    }
    if (lane == 0) { redz[warp] = zs; redm[warp] = ms; }
    __syncthreads();
    if (tid == 0) {
        float tz = 0.0f, tm = 0.0f;
        for (int w = 0; w < 8; w++) { tz += redz[w]; tm += redm[w]; }
        bc[1] = 1.0f / (tm + kEps * tz);
    }
    __syncthreads();
    const float inv = bc[1];
#pragma unroll
    for (int i = 0; i < 4; i++)
        row[tid + i * 256] = e[i] * mv[i] * inv;
}

// U[b,h] = prob[b,h] @ h[b].  batch=256, 256x256x1024 (NN).
__global__ __launch_bounds__(256) void u_kernel()
{
    __shared__ float As[8 * 132], Bs[8 * 132];
    float acc[8][8] = {};
    const int z = blockIdx.z, b = z >> 3;
    const int row0 = blockIdx.y * 128, col0 = blockIdx.x * 128;
    gemm_mainloop<false, false>(g_S + (size_t)z * kA * kN,
                                g_h + (size_t)b * kN * kD,
                                kN, kD, kN, row0, col0, acc, As, Bs);
    gemm_epilogue(g_U + (size_t)z * kA * kD, kD, row0, col0, acc, 1.0f, nullptr);
}

// out[b] = 1/8 * sum_h U[b,h] @ WV_h.  batch=32, 256x256 with K=8*256 (NN).
__global__ __launch_bounds__(256) void out_kernel(
    const float* __restrict__ WV, float* __restrict__ out)
{
    __shared__ float As[8 * 132], Bs[8 * 132];
    float acc[8][8] = {};
    const int b = blockIdx.z;
    const int row0 = blockIdx.y * 128, col0 = blockIdx.x * 128;
    for (int hh = 0; hh < 8; hh++) {
        gemm_mainloop<false, false>(g_U + (size_t)(b * 8 + hh) * kA * kD,
                                    WV + (size_t)hh * kD * kD,
                                    kD, kD, kD, row0, col0, acc, As, Bs);
    }
    gemm_epilogue(out + (size_t)b * kA * kD, kD, row0, col0, acc, 0.125f, nullptr);
}

// ---------------------------------------------------------------------------
extern "C" void kernel_launch(void* const* d_in, const int* in_sizes, int n_in,
                              void* d_out, int out_size)
{
    const float* x     = (const float*)d_in[0];
    const float* m     = (const float*)d_in[1];
    const float* W_enc = (const float*)d_in[2];
    const float* b_enc = (const float*)d_in[3];
    const float* WQ    = (const float*)d_in[4];
    const float* WK    = (const float*)d_in[5];
    const float* WV    = (const float*)d_in[6];
    float* out = (float*)d_out;

    enc_kernel<<<dim3(2, 256, 1), 256>>>(x, W_enc, b_enc);
    m_kernel<<<dim3(2, 2, 8), 256>>>(WQ, WK);
    g_kernel<<<dim3(2, 2, 256), 256>>>();
    s_kernel<<<dim3(8, 2, 256), 256>>>();
    softmax_kernel<<<dim3(65536, 1, 1), 256>>>(m);
    u_kernel<<<dim3(2, 2, 256), 256>>>();
    out_kernel<<<dim3(2, 2, 32), 256>>>(WV, out);
}

// round 3
// speedup vs baseline: 2.7495x; 2.7495x over previous
#include <cuda_runtime.h>
#include <cuda_bf16.h>
#include <cstdint>

using bf16 = __nv_bfloat16;

// ===========================================================================
// MHA_73607149519311 — round 3: split-bf16 (3xBF16) GEMMs on mma.sync HMMA.
// (tcgen05 unavailable: harness builds via compute_103 PTX, no 'a' features)
//
//   every GEMM operand X stored as X_hi + X_lo (bf16); each K=16 step issues
//   hi*hi + hi*lo + lo*hi into fp32 accumulators -> fp32-equivalent GEMMs.
//
// Pipeline:
//   conv_x      : x -> leaky -> split
//   conv_wenc   : W_enc -> split
//   conv_wvt    : WVT_cat[e][h*256+d] = WV[h][d][e] -> split
//   mt_kernel   : MT[h] = WK_h @ WQ_h^T (SIMT fp32) -> split
//   enc_mma     : h = x_sp @ Wenc_sp^T + b            (NT, K=256)
//   transpose_h : h_sp [n,d] -> h_spT [d,n]
//   g_mma       : G[bh] = ha_sp[b] @ MT_sp[h]^T       (NT, K=256)
//   s_mma       : S[bh] = G_sp[bh] @ h_sp[b]^T *SCALE (NT, K=256) -> fp32
//   softmax     : prob = e*m / (sum e*m + eps*Z) -> split
//   u_mma       : Ucat[b][a][h*256+d] = prob @ h      (NT vs h_spT, K=1024)
//   out_mma     : out[b] = 1/8 * Ucat[b] @ WVT_cat^T  (NT, K=2048)
// ===========================================================================

namespace {
constexpr float kScale = 1.0f / 16.0f;   // 1/sqrt(256)
constexpr float kEps   = 1e-12f;
}

// ---- scratch (static device globals; no dynamic allocation) ----
#define DEVBUF(name, count) __device__ __align__(128) bf16 name[count]
DEVBUF(g_xh, 8388608);  DEVBUF(g_xl, 8388608);    // leaky(x) split   [32768,256]
DEVBUF(g_weh, 65536);   DEVBUF(g_wel, 65536);     // W_enc split      [256,256]
DEVBUF(g_mth, 524288);  DEVBUF(g_mtl, 524288);    // MT=WK@WQ^T split [8,256,256]
DEVBUF(g_hh, 8388608);  DEVBUF(g_hl, 8388608);    // h split          [32,1024,256]
DEVBUF(g_hth, 8388608); DEVBUF(g_htl, 8388608);   // h^T split        [32,256,1024]
DEVBUF(g_gh, 16777216); DEVBUF(g_gl, 16777216);   // G split          [256,256,256]
DEVBUF(g_ph, 67108864); DEVBUF(g_pl, 67108864);   // prob split       [256,256,1024]
DEVBUF(g_uh, 16777216); DEVBUF(g_ul, 16777216);   // U concat split   [32,256,2048]
DEVBUF(g_wvh, 524288);  DEVBUF(g_wvl, 524288);    // WVT_cat split    [256,2048]
__device__ __align__(128) float g_S[67108864];     // S fp32           [256,256,1024]

// ============================= helpers =====================================
__device__ __forceinline__ uint32_t s2u(const void* p) {
    uint32_t a;
    asm("{ .reg .u64 t; cvta.to.shared.u64 t, %1; cvt.u32.u64 %0, t; }"
        : "=r"(a) : "l"(p));
    return a;
}

__device__ __forceinline__ void cp16(uint32_t saddr, const void* gaddr) {
    asm volatile("cp.async.cg.shared.global [%0], [%1], 16;"
                 :: "r"(saddr), "l"(gaddr) : "memory");
}
#define CP_COMMIT() asm volatile("cp.async.commit_group;" ::: "memory")
#define CP_WAIT1()  asm volatile("cp.async.wait_group 1;" ::: "memory")
#define CP_WAIT0()  asm volatile("cp.async.wait_group 0;" ::: "memory")

__device__ __forceinline__ void ldmx4(uint32_t* r, uint32_t addr) {
    asm volatile("ldmatrix.sync.aligned.m8n8.x4.shared.b16 {%0,%1,%2,%3}, [%4];"
                 : "=r"(r[0]), "=r"(r[1]), "=r"(r[2]), "=r"(r[3]) : "r"(addr));
}

__device__ __forceinline__ void mma16816(float* c, const uint32_t* a,
                                         uint32_t b0, uint32_t b1) {
    asm volatile(
        "mma.sync.aligned.m16n8k16.row.col.f32.bf16.bf16.f32 "
        "{%0,%1,%2,%3}, {%4,%5,%6,%7}, {%8,%9}, {%0,%1,%2,%3};"
        : "+f"(c[0]), "+f"(c[1]), "+f"(c[2]), "+f"(c[3])
        : "r"(a[0]), "r"(a[1]), "r"(a[2]), "r"(a[3]), "r"(b0), "r"(b1));
}

__device__ __forceinline__ void split2(float v, bf16& hi, bf16& lo) {
    hi = __float2bfloat16(v);
    lo = __float2bfloat16(v - __bfloat162float(hi));
}
__device__ __forceinline__ uint32_t packbf2(bf16 a, bf16 b) {
    __nv_bfloat162 t; t.x = a; t.y = b;
    return *reinterpret_cast<uint32_t*>(&t);
}

// ============================ MMA mainloop =================================
// 128x128 CTA tile, NT split-bf16 GEMM. 256 threads = 8 warps (2 M x 4 N),
// warp tile 64x32. cp.async double-buffered, K chunks of 64.
// SMEM stage: Ahi | Alo | Bhi | Blo, 16KB each (128 rows x 128B, XOR-swizzled).

__device__ __forceinline__ void issue_chunk(
    const bf16* __restrict__ Ah, const bf16* __restrict__ Al, int lda,
    const bf16* __restrict__ Bh, const bf16* __restrict__ Bl, int ldb,
    int row0, int col0, int kt, uint32_t sb)
{
    const int tid = threadIdx.x;
    const int lr = tid >> 3, lcb = tid & 7;
#pragma unroll
    for (int i = 0; i < 4; i++) {
        const int r = lr + i * 32;
        uint32_t off = (uint32_t)(r * 128 + lcb * 16);
        off ^= (off >> 3) & 0x70;
        const size_t ga = (size_t)(row0 + r) * lda + kt + lcb * 8;
        const size_t gb = (size_t)(col0 + r) * ldb + kt + lcb * 8;
        cp16(sb + off,         Ah + ga);
        cp16(sb + 16384 + off, Al + ga);
        cp16(sb + 32768 + off, Bh + gb);
        cp16(sb + 49152 + off, Bl + gb);
    }
    CP_COMMIT();
}

__device__ __forceinline__ void mma_nt_mainloop(
    const bf16* __restrict__ Ah, const bf16* __restrict__ Al, int lda,
    const bf16* __restrict__ Bh, const bf16* __restrict__ Bl, int ldb,
    int row0, int col0, int K, uint32_t sdu, float (&c)[4][4][4])
{
    const int tid = threadIdx.x;
    const int lane = tid & 31, wid = tid >> 5;
    const int wm = (wid & 1) << 6;          // warp M offset (0/64)
    const int wn = (wid >> 1) << 5;         // warp N offset (0/32/64/96)

    // ldmatrix lane addressing (row within 128-row tile, 16B segment)
    const int arow0 = wm + (lane & 15);                       // + mi*16
    const uint32_t aseg = (uint32_t)((lane >> 4) << 4);
    const int brow0 = wn + ((lane >> 4) << 3) + (lane & 7);   // + nj*16
    const uint32_t bseg = (uint32_t)(((lane >> 3) & 1) << 4);

    issue_chunk(Ah, Al, lda, Bh, Bl, ldb, row0, col0, 0, sdu);

    const int NC = K >> 6;
    for (int ci = 0; ci < NC; ci++) {
        if (ci + 1 < NC) {
            issue_chunk(Ah, Al, lda, Bh, Bl, ldb, row0, col0,
                        (ci + 1) << 6, sdu + ((ci + 1) & 1) * 65536);
            CP_WAIT1();
        } else {
            CP_WAIT0();
        }
        __syncthreads();

        const uint32_t sb = sdu + (ci & 1) * 65536;
#pragma unroll
        for (int k = 0; k < 4; k++) {
            const uint32_t kb = (uint32_t)(k << 5);     // k16 byte offset
            uint32_t afh[4][4], afl[4][4];
#pragma unroll
            for (int mi = 0; mi < 4; mi++) {
                const int r = arow0 + mi * 16;
                const uint32_t off = (uint32_t)(r << 7)
                                   + ((kb + aseg) ^ (uint32_t)((r & 7) << 4));
                ldmx4(afh[mi], sb + off);
                ldmx4(afl[mi], sb + 16384 + off);
            }
            uint32_t bfh[2][4], bfl[2][4];
#pragma unroll
            for (int nj = 0; nj < 2; nj++) {
                const int r = brow0 + nj * 16;
                const uint32_t off = (uint32_t)(r << 7)
                                   + ((kb + bseg) ^ (uint32_t)((r & 7) << 4));
                ldmx4(bfh[nj], sb + 32768 + off);
                ldmx4(bfl[nj], sb + 49152 + off);
            }
#pragma unroll
            for (int mi = 0; mi < 4; mi++)
#pragma unroll
                for (int ni = 0; ni < 4; ni++) {
                    const int nj = ni >> 1, o = (ni & 1) << 1;
                    mma16816(c[mi][ni], afh[mi], bfh[nj][o], bfh[nj][o + 1]);
                    mma16816(c[mi][ni], afh[mi], bfl[nj][o], bfl[nj][o + 1]);
                    mma16816(c[mi][ni], afl[mi], bfh[nj][o], bfh[nj][o + 1]);
                }
        }
        __syncthreads();
    }
}

// Epilogue index helpers: element q of c[mi][ni]:
//   row = wm + mi*16 + (lane>>2) + (q>=2 ? 8 : 0)
//   col = wn + ni*8 + (lane&3)*2 + (q&1)       (pairs q={0,1},{2,3} contiguous)

// ============================ conversion kernels ===========================

__global__ __launch_bounds__(256) void conv_x_kernel(const float* __restrict__ x) {
    size_t idx = (size_t)blockIdx.x * 256 + threadIdx.x;   // over float4s
    float4 v = ((const float4*)x)[idx];
    v.x = v.x > 0.f ? v.x : 0.01f * v.x;
    v.y = v.y > 0.f ? v.y : 0.01f * v.y;
    v.z = v.z > 0.f ? v.z : 0.01f * v.z;
    v.w = v.w > 0.f ? v.w : 0.01f * v.w;
    bf16 h0,l0,h1,l1,h2,l2,h3,l3;
    split2(v.x,h0,l0); split2(v.y,h1,l1); split2(v.z,h2,l2); split2(v.w,h3,l3);
    *(uint2*)(g_xh + idx * 4) = make_uint2(packbf2(h0,h1), packbf2(h2,h3));
    *(uint2*)(g_xl + idx * 4) = make_uint2(packbf2(l0,l1), packbf2(l2,l3));
}

__global__ __launch_bounds__(256) void conv_wenc_kernel(const float* __restrict__ W) {
    size_t idx = (size_t)blockIdx.x * 256 + threadIdx.x;   // 16384 float4s
    float4 v = ((const float4*)W)[idx];
    bf16 h0,l0,h1,l1,h2,l2,h3,l3;
    split2(v.x,h0,l0); split2(v.y,h1,l1); split2(v.z,h2,l2); split2(v.w,h3,l3);
    *(uint2*)(g_weh + idx * 4) = make_uint2(packbf2(h0,h1), packbf2(h2,h3));
    *(uint2*)(g_wel + idx * 4) = make_uint2(packbf2(l0,l1), packbf2(l2,l3));
}

// WVT_cat[e][h*256+d] = WV[h][d][e]
__global__ __launch_bounds__(256) void conv_wvt_kernel(const float* __restrict__ WV) {
    size_t o = (size_t)blockIdx.x * 256 + threadIdx.x;     // 524288 elems
    int e = (int)(o >> 11);
    int k = (int)(o & 2047);                                // h*256+d
    float v = WV[(size_t)k * 256 + e];
    bf16 hi, lo; split2(v, hi, lo);
    g_wvh[o] = hi; g_wvl[o] = lo;
}

// ---- SIMT fp32 GEMM for MT = WK @ WQ^T (tiny) ----
__global__ __launch_bounds__(256) void mt_kernel(const float* __restrict__ WQ,
                                                 const float* __restrict__ WK) {
    __shared__ float As[8 * 132], Bs[8 * 132];
    float acc[8][8] = {};
    const int hh = blockIdx.z;
    const int row0 = blockIdx.y * 128, col0 = blockIdx.x * 128;
    const float* A = WK + (size_t)hh * 65536;
    const float* B = WQ + (size_t)hh * 65536;
    const int tid = threadIdx.x;
    const int am = tid >> 1, ak = (tid & 1) << 2;
    const int tx = tid & 15, ty = tid >> 4;
    const float* aP = A + (size_t)(row0 + am) * 256 + ak;
    const float* bP = B + (size_t)(col0 + am) * 256 + ak;
    for (int kt = 0; kt < 256; kt += 8) {
        float4 av = *(const float4*)(aP + kt);
        As[(ak+0)*132+am]=av.x; As[(ak+1)*132+am]=av.y;
        As[(ak+2)*132+am]=av.z; As[(ak+3)*132+am]=av.w;
        float4 bv = *(const float4*)(bP + kt);
        Bs[(ak+0)*132+am]=bv.x; Bs[(ak+1)*132+am]=bv.y;
        Bs[(ak+2)*132+am]=bv.z; Bs[(ak+3)*132+am]=bv.w;
        __syncthreads();
#pragma unroll
        for (int k = 0; k < 8; k++) {
            float ar[8], br[8];
            *(float4*)(ar)   = *(const float4*)(As + k*132 + ty*8);
            *(float4*)(ar+4) = *(const float4*)(As + k*132 + ty*8 + 4);
            *(float4*)(br)   = *(const float4*)(Bs + k*132 + tx*8);
            *(float4*)(br+4) = *(const float4*)(Bs + k*132 + tx*8 + 4);
#pragma unroll
            for (int i = 0; i < 8; i++)
#pragma unroll
                for (int j = 0; j < 8; j++)
                    acc[i][j] = fmaf(ar[i], br[j], acc[i][j]);
        }
        __syncthreads();
    }
    bf16* Dh = g_mth + (size_t)hh * 65536;
    bf16* Dl = g_mtl + (size_t)hh * 65536;
#pragma unroll
    for (int i = 0; i < 8; i++) {
        size_t base = (size_t)(row0 + ty*8 + i) * 256 + col0 + tx*8;
#pragma unroll
        for (int j = 0; j < 8; j += 2) {
            bf16 h0,l0,h1,l1;
            split2(acc[i][j],h0,l0); split2(acc[i][j+1],h1,l1);
            *(uint32_t*)(Dh + base + j) = packbf2(h0,h1);
            *(uint32_t*)(Dl + base + j) = packbf2(l0,l1);
        }
    }
}

// ============================== MMA kernels ================================

// h = x_sp @ Wenc^T + b. grid (2, 256).
__global__ __launch_bounds__(256, 1) void enc_mma_kernel(const float* __restrict__ bias) {
    extern __shared__ char sd[];
    const uint32_t sdu = s2u(sd);
    float c[4][4][4] = {};
    const int row0 = blockIdx.y * 128, col0 = blockIdx.x * 128;
    mma_nt_mainloop(g_xh, g_xl, 256, g_weh, g_wel, 256, row0, col0, 256, sdu, c);
    const int lane = threadIdx.x & 31, wid = threadIdx.x >> 5;
    const int wm = (wid & 1) << 6, wn = (wid >> 1) << 5;
#pragma unroll
    for (int mi = 0; mi < 4; mi++)
#pragma unroll
        for (int ni = 0; ni < 4; ni++) {
            const int col = col0 + wn + ni * 8 + (lane & 3) * 2;
            const float b0 = bias[col], b1 = bias[col + 1];
#pragma unroll
            for (int q = 0; q < 2; q++) {
                const int row = row0 + wm + mi * 16 + (lane >> 2) + q * 8;
                const float v0 = c[mi][ni][q * 2]     + b0;
                const float v1 = c[mi][ni][q * 2 + 1] + b1;
                bf16 h0,l0,h1,l1; split2(v0,h0,l0); split2(v1,h1,l1);
                const size_t p = (size_t)row * 256 + col;
                *(uint32_t*)(g_hh + p) = packbf2(h0,h1);
                *(uint32_t*)(g_hl + p) = packbf2(l0,l1);
            }
        }
}

// h_sp [b][n][d] -> h_spT [b][d][n].
__global__ __launch_bounds__(256) void transpose_h_kernel() {
    __shared__ bf16 t[64 * 65];
    const int d0 = blockIdx.x * 64, n0 = blockIdx.y * 64, b = blockIdx.z;
    const int tid = threadIdx.x;
    const bf16* ins[2]  = { g_hh, g_hl };
    bf16*       outs[2] = { g_hth, g_htl };
#pragma unroll
    for (int p = 0; p < 2; p++) {
        const bf16* in = ins[p] + (size_t)b * 1024 * 256;
        bf16* out      = outs[p] + (size_t)b * 256 * 1024;
#pragma unroll
        for (int i = 0; i < 8; i++) {
            int idx = tid + i * 256;
            int r = idx >> 5, c2 = idx & 31;
            uint32_t v = *(const uint32_t*)(in + (size_t)(n0 + r) * 256 + d0 + c2 * 2);
            __nv_bfloat162 bv = *reinterpret_cast<__nv_bfloat162*>(&v);
            t[r * 65 + c2 * 2]     = bv.x;
            t[r * 65 + c2 * 2 + 1] = bv.y;
        }
        __syncthreads();
#pragma unroll
        for (int i = 0; i < 8; i++) {
            int idx = tid + i * 256;
            int r = idx >> 5, c2 = idx & 31;
            uint32_t w = packbf2(t[(c2 * 2) * 65 + r], t[(c2 * 2 + 1) * 65 + r]);
            *(uint32_t*)(out + (size_t)(d0 + r) * 1024 + n0 + c2 * 2) = w;
        }
        __syncthreads();
    }
}

// G[bh] = ha_sp[b] @ MT[h]^T. grid (2, 2, 256).
__global__ __launch_bounds__(256, 1) void g_mma_kernel() {
    extern __shared__ char sd[];
    const uint32_t sdu = s2u(sd);
    float c[4][4][4] = {};
    const int z = blockIdx.z, b = z >> 3, hh = z & 7;
    const int row0 = blockIdx.y * 128, col0 = blockIdx.x * 128;
    mma_nt_mainloop(g_hh + (size_t)b * 262144, g_hl + (size_t)b * 262144, 256,
                    g_mth + (size_t)hh * 65536, g_mtl + (size_t)hh * 65536, 256,
                    row0, col0, 256, sdu, c);
    const int lane = threadIdx.x & 31, wid = threadIdx.x >> 5;
    const int wm = (wid & 1) << 6, wn = (wid >> 1) << 5;
    bf16* Dh = g_gh + (size_t)z * 65536;
    bf16* Dl = g_gl + (size_t)z * 65536;
#pragma unroll
    for (int mi = 0; mi < 4; mi++)
#pragma unroll
        for (int ni = 0; ni < 4; ni++) {
            const int col = col0 + wn + ni * 8 + (lane & 3) * 2;
#pragma unroll
            for (int q = 0; q < 2; q++) {
                const int row = row0 + wm + mi * 16 + (lane >> 2) + q * 8;
                bf16 h0,l0,h1,l1;
                split2(c[mi][ni][q*2],h0,l0); split2(c[mi][ni][q*2+1],h1,l1);
                const size_t p = (size_t)row * 256 + col;
                *(uint32_t*)(Dh + p) = packbf2(h0,h1);
                *(uint32_t*)(Dl + p) = packbf2(l0,l1);
            }
        }
}

// S[bh] = G[bh] @ h[b]^T * SCALE -> fp32. grid (8, 2, 256).
__global__ __launch_bounds__(256, 1) void s_mma_kernel() {
    extern __shared__ char sd[];
    const uint32_t sdu = s2u(sd);
    float c[4][4][4] = {};
    const int z = blockIdx.z, b = z >> 3;
    const int row0 = blockIdx.y * 128, col0 = blockIdx.x * 128;
    mma_nt_mainloop(g_gh + (size_t)z * 65536, g_gl + (size_t)z * 65536, 256,
                    g_hh + (size_t)b * 262144, g_hl + (size_t)b * 262144, 256,
                    row0, col0, 256, sdu, c);
    const int lane = threadIdx.x & 31, wid = threadIdx.x >> 5;
    const int wm = (wid & 1) << 6, wn = (wid >> 1) << 5;
    float* D = g_S + (size_t)z * 262144;
#pragma unroll
    for (int mi = 0; mi < 4; mi++)
#pragma unroll
        for (int ni = 0; ni < 4; ni++) {
            const int col = col0 + wn + ni * 8 + (lane & 3) * 2;
#pragma unroll
            for (int q = 0; q < 2; q++) {
                const int row = row0 + wm + mi * 16 + (lane >> 2) + q * 8;
                float2 v;
                v.x = kScale * c[mi][ni][q*2];
                v.y = kScale * c[mi][ni][q*2+1];
                *(float2*)(D + (size_t)row * 1024 + col) = v;
            }
        }
}

// prob = e*m / (sum(e*m) + eps*Z), split-bf16 output.
__global__ __launch_bounds__(256) void softmax_kernel(const float* __restrict__ mglob) {
    const int idx = blockIdx.x;          // (b*8+h)*256 + a
    const int a = idx & 255, b = idx >> 11;
    const float* row = g_S + (size_t)idx * 1024;
    const float* mrow = mglob + ((size_t)b * 256 + a) * 1024;
    const int tid = threadIdx.x;

    float4 v = ((const float4*)row)[tid];
    float4 mv = ((const float4*)mrow)[tid];
    float lmax = fmaxf(fmaxf(v.x, v.y), fmaxf(v.z, v.w));
#pragma unroll
    for (int o = 16; o > 0; o >>= 1)
        lmax = fmaxf(lmax, __shfl_xor_sync(0xffffffffu, lmax, o));

    __shared__ float redmax[8], redz[8], redm[8], bc[2];
    const int warp = tid >> 5, lane = tid & 31;
    if (lane == 0) redmax[warp] = lmax;
    __syncthreads();
    if (tid == 0) {
        float mx = redmax[0];
        for (int w = 1; w < 8; w++) mx = fmaxf(mx, redmax[w]);
        bc[0] = mx;
    }
    __syncthreads();
    const float mx = bc[0];

    float e0 = __expf(v.x - mx), e1 = __expf(v.y - mx);
    float e2 = __expf(v.z - mx), e3 = __expf(v.w - mx);
    float zs = e0 + e1 + e2 + e3;
    float ms = e0 * mv.x + e1 * mv.y + e2 * mv.z + e3 * mv.w;
#pragma unroll
    for (int o = 16; o > 0; o >>= 1) {
        zs += __shfl_xor_sync(0xffffffffu, zs, o);
        ms += __shfl_xor_sync(0xffffffffu, ms, o);
    }
    if (lane == 0) { redz[warp] = zs; redm[warp] = ms; }
    __syncthreads();
    if (tid == 0) {
        float tz = 0.f, tm = 0.f;
        for (int w = 0; w < 8; w++) { tz += redz[w]; tm += redm[w]; }
        bc[1] = 1.0f / (tm + kEps * tz);
    }
    __syncthreads();
    const float inv = bc[1];

    float p0 = e0 * mv.x * inv, p1 = e1 * mv.y * inv;
    float p2 = e2 * mv.z * inv, p3 = e3 * mv.w * inv;
    bf16 h0,l0,h1,l1,h2,l2,h3,l3;
    split2(p0,h0,l0); split2(p1,h1,l1); split2(p2,h2,l2); split2(p3,h3,l3);
    size_t base = (size_t)idx * 1024 + 4 * tid;
    *(uint2*)(g_ph + base) = make_uint2(packbf2(h0,h1), packbf2(h2,h3));
    *(uint2*)(g_pl + base) = make_uint2(packbf2(l0,l1), packbf2(l2,l3));
}

// Ucat[b][a][h*256+d] = prob[bh] @ h[b].  grid (2, 2, 256), K=1024.
__global__ __launch_bounds__(256, 1) void u_mma_kernel() {
    extern __shared__ char sd[];
    const uint32_t sdu = s2u(sd);
    float c[4][4][4] = {};
    const int z = blockIdx.z, b = z >> 3, hh = z & 7;
    const int row0 = blockIdx.y * 128, col0 = blockIdx.x * 128;
    mma_nt_mainloop(g_ph + (size_t)z * 262144, g_pl + (size_t)z * 262144, 1024,
                    g_hth + (size_t)b * 262144, g_htl + (size_t)b * 262144, 1024,
                    row0, col0, 1024, sdu, c);
    const int lane = threadIdx.x & 31, wid = threadIdx.x >> 5;
    const int wm = (wid & 1) << 6, wn = (wid >> 1) << 5;
#pragma unroll
    for (int mi = 0; mi < 4; mi++)
#pragma unroll
        for (int ni = 0; ni < 4; ni++) {
            const int col = col0 + wn + ni * 8 + (lane & 3) * 2;
#pragma unroll
            for (int q = 0; q < 2; q++) {
                const int row = row0 + wm + mi * 16 + (lane >> 2) + q * 8;
                bf16 h0,l0,h1,l1;
                split2(c[mi][ni][q*2],h0,l0); split2(c[mi][ni][q*2+1],h1,l1);
                const size_t p = ((size_t)b * 256 + row) * 2048 + hh * 256 + col;
                *(uint32_t*)(g_uh + p) = packbf2(h0,h1);
                *(uint32_t*)(g_ul + p) = packbf2(l0,l1);
            }
        }
}

// out[b] = 1/8 * Ucat[b] @ WVT_cat^T.  grid (2, 2, 32), K=2048.
__global__ __launch_bounds__(256, 1) void out_mma_kernel(float* __restrict__ out) {
    extern __shared__ char sd[];
    const uint32_t sdu = s2u(sd);
    float c[4][4][4] = {};
    const int b = blockIdx.z;
    const int row0 = blockIdx.y * 128, col0 = blockIdx.x * 128;
    mma_nt_mainloop(g_uh + (size_t)b * 524288, g_ul + (size_t)b * 524288, 2048,
                    g_wvh, g_wvl, 2048, row0, col0, 2048, sdu, c);
    const int lane = threadIdx.x & 31, wid = threadIdx.x >> 5;
    const int wm = (wid & 1) << 6, wn = (wid >> 1) << 5;
    float* D = out + (size_t)b * 65536;
#pragma unroll
    for (int mi = 0; mi < 4; mi++)
#pragma unroll
        for (int ni = 0; ni < 4; ni++) {
            const int col = col0 + wn + ni * 8 + (lane & 3) * 2;
#pragma unroll
            for (int q = 0; q < 2; q++) {
                const int row = row0 + wm + mi * 16 + (lane >> 2) + q * 8;
                float2 v;
                v.x = 0.125f * c[mi][ni][q*2];
                v.y = 0.125f * c[mi][ni][q*2+1];
                *(float2*)(D + (size_t)row * 256 + col) = v;
            }
        }
}

// ===========================================================================
extern "C" void kernel_launch(void* const* d_in, const int* in_sizes, int n_in,
                              void* d_out, int out_size)
{
    const float* x     = (const float*)d_in[0];
    const float* m     = (const float*)d_in[1];
    const float* W_enc = (const float*)d_in[2];
    const float* b_enc = (const float*)d_in[3];
    const float* WQ    = (const float*)d_in[4];
    const float* WK    = (const float*)d_in[5];
    const float* WV    = (const float*)d_in[6];
    float* out = (float*)d_out;

    constexpr int kDynSmem = 131072;   // 2 stages x 4 tiles x 16KB
    cudaFuncSetAttribute(enc_mma_kernel, cudaFuncAttributeMaxDynamicSharedMemorySize, kDynSmem);
    cudaFuncSetAttribute(g_mma_kernel,   cudaFuncAttributeMaxDynamicSharedMemorySize, kDynSmem);
    cudaFuncSetAttribute(s_mma_kernel,   cudaFuncAttributeMaxDynamicSharedMemorySize, kDynSmem);
    cudaFuncSetAttribute(u_mma_kernel,   cudaFuncAttributeMaxDynamicSharedMemorySize, kDynSmem);
    cudaFuncSetAttribute(out_mma_kernel, cudaFuncAttributeMaxDynamicSharedMemorySize, kDynSmem);

    conv_x_kernel<<<8192, 256>>>(x);
    conv_wenc_kernel<<<64, 256>>>(W_enc);
    conv_wvt_kernel<<<2048, 256>>>(WV);
    mt_kernel<<<dim3(2, 2, 8), 256>>>(WQ, WK);

    enc_mma_kernel<<<dim3(2, 256, 1), 256, kDynSmem>>>(b_enc);
    transpose_h_kernel<<<dim3(4, 16, 32), 256>>>();
    g_mma_kernel<<<dim3(2, 2, 256), 256, kDynSmem>>>();
    s_mma_kernel<<<dim3(8, 2, 256), 256, kDynSmem>>>();
    softmax_kernel<<<65536, 256>>>(m);
    u_mma_kernel<<<dim3(2, 2, 256), 256, kDynSmem>>>();
    out_mma_kernel<<<dim3(2, 2, 32), 256, kDynSmem>>>(out);
}